// round 2
// baseline (speedup 1.0000x reference)
#include <cuda_runtime.h>
#include <cuda_bf16.h>
#include <math.h>

// ---------------- problem constants ----------------
#define Bsz   128
#define NTOK  64
#define Cdim  784
#define NHd   8
#define HD    98          // Cdim / NHd
#define HID   3136
#define ROWS  (Bsz*NTOK)  // 8192
#define BFC   64
#define Hsp   28
#define Wsp   28
#define NREG  49
#define TOPK  4
#define OUT_OFF (Bsz*NTOK*Cdim)   // 6422528

// ---------------- scratch (device globals; no allocations) ----------------
__device__ float g_h   [ROWS*Cdim];
__device__ float g_qkv [ROWS*3*Cdim];
__device__ float g_att [ROWS*Cdim];
__device__ float g_o   [ROWS*Cdim];
__device__ float g_xr  [ROWS*Cdim];
__device__ float g_h2  [ROWS*Cdim];
__device__ float g_hid [ROWS*HID];
__device__ float g_bfqkv[Bsz*192*784];
__device__ float g_attg [Bsz*64*784];
__device__ float g_qr  [Bsz*64*NREG];
__device__ float g_kr  [Bsz*64*NREG];
__device__ int   g_idx [Bsz*NREG*TOPK];

// ---------------- LayerNorm (one block per row of 784) ----------------
__global__ void ln_kernel(const float* __restrict__ x,
                          const float* __restrict__ g, const float* __restrict__ b,
                          float* __restrict__ out) {
    int row = blockIdx.x;
    const float* xr = x + (size_t)row * Cdim;
    __shared__ float buf[Cdim];
    __shared__ float rs[2];
    float s = 0.f, ss = 0.f;
    for (int i = threadIdx.x; i < Cdim; i += blockDim.x) {
        float v = xr[i]; buf[i] = v; s += v; ss += v * v;
    }
    // warp + smem reduce
    __shared__ float red[64];
    for (int o = 16; o > 0; o >>= 1) { s += __shfl_down_sync(0xffffffffu, s, o); ss += __shfl_down_sync(0xffffffffu, ss, o); }
    int wid = threadIdx.x >> 5, lid = threadIdx.x & 31;
    if (lid == 0) { red[wid] = s; red[wid + 32] = ss; }
    __syncthreads();
    if (threadIdx.x == 0) {
        float t = 0.f, tt = 0.f;
        int nw = blockDim.x >> 5;
        for (int i = 0; i < nw; i++) { t += red[i]; tt += red[i + 32]; }
        float mean = t / Cdim;
        float var  = tt / Cdim - mean * mean;
        rs[0] = mean; rs[1] = rsqrtf(var + 1e-5f);
    }
    __syncthreads();
    float mean = rs[0], inv = rs[1];
    float* o = out + (size_t)row * Cdim;
    for (int i = threadIdx.x; i < Cdim; i += blockDim.x)
        o[i] = (buf[i] - mean) * inv * g[i] + b[i];
}

// LN2: in = o + x (residual), also writes xr
__global__ void ln2_kernel(const float* __restrict__ ov, const float* __restrict__ x,
                           const float* __restrict__ g, const float* __restrict__ b,
                           float* __restrict__ xr_out, float* __restrict__ out) {
    int row = blockIdx.x;
    const float* a = ov + (size_t)row * Cdim;
    const float* c = x  + (size_t)row * Cdim;
    __shared__ float buf[Cdim];
    __shared__ float rs[2];
    __shared__ float red[64];
    float s = 0.f, ss = 0.f;
    for (int i = threadIdx.x; i < Cdim; i += blockDim.x) {
        float v = a[i] + c[i];
        buf[i] = v;
        xr_out[(size_t)row * Cdim + i] = v;
        s += v; ss += v * v;
    }
    for (int o = 16; o > 0; o >>= 1) { s += __shfl_down_sync(0xffffffffu, s, o); ss += __shfl_down_sync(0xffffffffu, ss, o); }
    int wid = threadIdx.x >> 5, lid = threadIdx.x & 31;
    if (lid == 0) { red[wid] = s; red[wid + 32] = ss; }
    __syncthreads();
    if (threadIdx.x == 0) {
        float t = 0.f, tt = 0.f;
        int nw = blockDim.x >> 5;
        for (int i = 0; i < nw; i++) { t += red[i]; tt += red[i + 32]; }
        float mean = t / Cdim;
        float var  = tt / Cdim - mean * mean;
        rs[0] = mean; rs[1] = rsqrtf(var + 1e-5f);
    }
    __syncthreads();
    float mean = rs[0], inv = rs[1];
    float* o = out + (size_t)row * Cdim;
    for (int i = threadIdx.x; i < Cdim; i += blockDim.x)
        o[i] = (buf[i] - mean) * inv * g[i] + b[i];
}

// ---------------- generic tiled fp32 GEMM ----------------
// C[M,N] = A[M,K] @ B[K,N] (+bias) (+epilogue). M % 64 == 0, K % 16 == 0.
// EP: 0 = none, 1 = exact GELU, 2 = + residual
template<int EP>
__global__ void gemm_kernel(const float* __restrict__ A, const float* __restrict__ Bm,
                            const float* __restrict__ bias, const float* __restrict__ res,
                            float* __restrict__ C, int M, int N, int K) {
    __shared__ float As[16][64];
    __shared__ float Bs[16][68];
    int bx = blockIdx.x, by = blockIdx.y;
    int tid = threadIdx.x;
    int tx = tid & 15, ty = tid >> 4;
    int rowBase = by * 64, colBase = bx * 64;
    float acc[4][4] = {};
    for (int k0 = 0; k0 < K; k0 += 16) {
        #pragma unroll
        for (int i = 0; i < 4; i++) {
            int e = i * 256 + tid;
            int r = e >> 4, kk = e & 15;
            As[kk][r] = A[(size_t)(rowBase + r) * K + k0 + kk];
        }
        #pragma unroll
        for (int i = 0; i < 4; i++) {
            int e = i * 256 + tid;
            int kk = e >> 6, n = e & 63;
            int col = colBase + n;
            Bs[kk][n] = (col < N) ? Bm[(size_t)(k0 + kk) * N + col] : 0.f;
        }
        __syncthreads();
        #pragma unroll
        for (int kk = 0; kk < 16; kk++) {
            float a0 = As[kk][ty * 4 + 0], a1 = As[kk][ty * 4 + 1];
            float a2 = As[kk][ty * 4 + 2], a3 = As[kk][ty * 4 + 3];
            float b0 = Bs[kk][tx * 4 + 0], b1 = Bs[kk][tx * 4 + 1];
            float b2 = Bs[kk][tx * 4 + 2], b3 = Bs[kk][tx * 4 + 3];
            acc[0][0] += a0 * b0; acc[0][1] += a0 * b1; acc[0][2] += a0 * b2; acc[0][3] += a0 * b3;
            acc[1][0] += a1 * b0; acc[1][1] += a1 * b1; acc[1][2] += a1 * b2; acc[1][3] += a1 * b3;
            acc[2][0] += a2 * b0; acc[2][1] += a2 * b1; acc[2][2] += a2 * b2; acc[2][3] += a2 * b3;
            acc[3][0] += a3 * b0; acc[3][1] += a3 * b1; acc[3][2] += a3 * b2; acc[3][3] += a3 * b3;
        }
        __syncthreads();
    }
    #pragma unroll
    for (int i = 0; i < 4; i++) {
        int r = rowBase + ty * 4 + i;
        #pragma unroll
        for (int j = 0; j < 4; j++) {
            int c = colBase + tx * 4 + j;
            if (c < N) {
                float v = acc[i][j];
                if (bias) v += bias[c];
                if (EP == 1) v = 0.5f * v * (1.0f + erff(v * 0.70710678118654752440f));
                if (EP == 2) v += res[(size_t)r * N + c];
                C[(size_t)r * N + c] = v;
            }
        }
    }
}

// ---------------- MHA attention: one block per (head, batch) ----------------
__global__ void mha_kernel(const float* __restrict__ qkv, float* __restrict__ att) {
    extern __shared__ float sm[];
    float* Q  = sm;               // 64*98
    float* Kx = Q + 64 * HD;      // 64*98
    float* V  = Kx + 64 * HD;     // 64*98
    float* SC = V + 64 * HD;      // 64*64
    int h = blockIdx.x, b = blockIdx.y;
    int tid = threadIdx.x;
    const float* base = qkv + (size_t)(b * NTOK) * (3 * Cdim);
    for (int e = tid; e < 64 * HD; e += blockDim.x) {
        int t = e / HD, d = e % HD;
        Q[e]  = base[(size_t)t * (3 * Cdim) + h * HD + d];
        Kx[e] = base[(size_t)t * (3 * Cdim) + Cdim + h * HD + d];
        V[e]  = base[(size_t)t * (3 * Cdim) + 2 * Cdim + h * HD + d];
    }
    __syncthreads();
    const float scale = rsqrtf((float)HD);
    for (int e = tid; e < 64 * 64; e += blockDim.x) {
        int i = e >> 6, j = e & 63;
        float a = 0.f;
        const float* qi = Q + i * HD;
        const float* kj = Kx + j * HD;
        #pragma unroll 7
        for (int d = 0; d < HD; d++) a += qi[d] * kj[d];
        SC[e] = a * scale;
    }
    __syncthreads();
    if (tid < 64) {
        float* row = SC + tid * 64;
        float mx = -1e30f;
        for (int j = 0; j < 64; j++) mx = fmaxf(mx, row[j]);
        float s = 0.f;
        for (int j = 0; j < 64; j++) { float e = expf(row[j] - mx); row[j] = e; s += e; }
        float inv = 1.f / s;
        for (int j = 0; j < 64; j++) row[j] *= inv;
    }
    __syncthreads();
    for (int e = tid; e < 64 * HD; e += blockDim.x) {
        int i = e / HD, d = e % HD;
        float a = 0.f;
        const float* row = SC + i * 64;
        for (int j = 0; j < 64; j++) a += row[j] * V[j * HD + d];
        att[((size_t)(b * NTOK + i)) * Cdim + h * HD + d] = a;
    }
}

// ---------------- BiFormer qkv pointwise (64 -> 192 channels) ----------------
__global__ void bf_qkv_kernel(const float* __restrict__ o,
                              const float* __restrict__ w, const float* __restrict__ bias) {
    int y = blockIdx.x, b = blockIdx.y;
    __shared__ float xin[64][28];
    for (int e = threadIdx.x; e < 64 * 28; e += blockDim.x) {
        int c = e / 28, xx = e % 28;
        xin[c][xx] = o[((size_t)b * 64 + c) * 784 + y * 28 + xx];
    }
    __syncthreads();
    for (int e = threadIdx.x; e < 192 * 28; e += blockDim.x) {
        int oc = e / 28, xx = e % 28;
        float a = bias[oc];
        const float* wr = w + oc * 64;
        #pragma unroll 16
        for (int c = 0; c < 64; c++) a += xin[c][xx] * wr[c];
        g_bfqkv[((size_t)b * 192 + oc) * 784 + y * 28 + xx] = a;
    }
}

// ---------------- region average pooling of q, k ----------------
__global__ void bf_pool_kernel() {
    int b = blockIdx.x;
    for (int e = threadIdx.x; e < 64 * NREG; e += blockDim.x) {
        int c = e / NREG, r = e % NREG;
        int rh = r / 7, rw = r % 7;
        float sq = 0.f, sk = 0.f;
        const float* qc = g_bfqkv + ((size_t)b * 192 + c) * 784;
        const float* kc = g_bfqkv + ((size_t)b * 192 + 64 + c) * 784;
        for (int pr = 0; pr < 4; pr++)
            for (int pc = 0; pc < 4; pc++) {
                int s = (rh * 4 + pr) * 28 + rw * 4 + pc;
                sq += qc[s]; sk += kc[s];
            }
        g_qr[(b * 64 + c) * NREG + r] = sq * 0.0625f;
        g_kr[(b * 64 + c) * NREG + r] = sk * 0.0625f;
    }
}

// ---------------- region routing: top-4 per (b, r) ----------------
__global__ void bf_topk_kernel() {
    int r = blockIdx.x, b = blockIdx.y;
    __shared__ float qv[64];
    __shared__ float sc[NREG];
    int tid = threadIdx.x;
    if (tid < 64) qv[tid] = g_qr[(b * 64 + tid) * NREG + r];
    __syncthreads();
    if (tid < NREG) {
        float a = 0.f;
        for (int c = 0; c < 64; c++) a += qv[c] * g_kr[(b * 64 + c) * NREG + tid];
        sc[tid] = a;
    }
    __syncthreads();
    if (tid == 0) {
        for (int j = 0; j < TOPK; j++) {
            float mx = -1e30f; int mi = 0;
            for (int s = 0; s < NREG; s++) if (sc[s] > mx) { mx = sc[s]; mi = s; }
            sc[mi] = -1e30f;
            g_idx[(b * NREG + r) * TOPK + j] = mi;
        }
    }
}

// ---------------- BiFormer gathered attention: block per (r, h, b) ----------------
__global__ void bf_attn_kernel() {
    int r = blockIdx.x, h = blockIdx.y, b = blockIdx.z;
    __shared__ float q[16][8], kg[64][8], vg[64][8], sc[16][64];
    __shared__ int idx4[4];
    int tid = threadIdx.x;  // 128
    if (tid < 4) idx4[tid] = g_idx[(b * NREG + r) * TOPK + tid];
    int rh = r / 7, rw = r % 7;
    {
        int p = tid / 8, d = tid % 8;
        int s = (rh * 4 + p / 4) * 28 + rw * 4 + (p % 4);
        q[p][d] = g_bfqkv[((size_t)b * 192 + h * 8 + d) * 784 + s] * 0.125f;
    }
    __syncthreads();
    for (int e = tid; e < 512; e += 128) {
        int t = e / 8, d = e % 8;
        int reg = idx4[t / 16];
        int p2 = t % 16;
        int s = ((reg / 7) * 4 + p2 / 4) * 28 + (reg % 7) * 4 + (p2 % 4);
        kg[t][d] = g_bfqkv[((size_t)b * 192 + 64 + h * 8 + d) * 784 + s];
        vg[t][d] = g_bfqkv[((size_t)b * 192 + 128 + h * 8 + d) * 784 + s];
    }
    __syncthreads();
    for (int e = tid; e < 1024; e += 128) {
        int p = e >> 6, t = e & 63;
        float a = 0.f;
        #pragma unroll
        for (int d = 0; d < 8; d++) a += q[p][d] * kg[t][d];
        sc[p][t] = a;
    }
    __syncthreads();
    if (tid < 16) {
        float mx = -1e30f;
        for (int t = 0; t < 64; t++) mx = fmaxf(mx, sc[tid][t]);
        float s = 0.f;
        for (int t = 0; t < 64; t++) { float e = expf(sc[tid][t] - mx); sc[tid][t] = e; s += e; }
        float inv = 1.f / s;
        for (int t = 0; t < 64; t++) sc[tid][t] *= inv;
    }
    __syncthreads();
    {
        int p = tid / 8, d = tid % 8;
        float a = 0.f;
        for (int t = 0; t < 64; t++) a += sc[p][t] * vg[t][d];
        int s = (rh * 4 + p / 4) * 28 + rw * 4 + (p % 4);
        g_attg[((size_t)b * 64 + h * 8 + d) * 784 + s] = a;
    }
}

// ---------------- LePE (3x3 depthwise on v) + add + output projection ----------------
__global__ void bf_out_kernel(const float* __restrict__ lepe_w, const float* __restrict__ lepe_b,
                              const float* __restrict__ out_w, const float* __restrict__ out_b,
                              float* __restrict__ outp) {
    int y = blockIdx.x, b = blockIdx.y;
    __shared__ float v3[3][64][28];
    __shared__ float tmp[64][28];
    int tid = threadIdx.x;
    for (int ry = 0; ry < 3; ry++) {
        int yy = y + ry - 1;
        for (int e = tid; e < 64 * 28; e += blockDim.x) {
            int c = e / 28, xx = e % 28;
            v3[ry][c][xx] = (yy >= 0 && yy < 28)
                ? g_bfqkv[((size_t)b * 192 + 128 + c) * 784 + yy * 28 + xx] : 0.f;
        }
    }
    __syncthreads();
    for (int e = tid; e < 64 * 28; e += blockDim.x) {
        int c = e / 28, xx = e % 28;
        float a = g_attg[((size_t)b * 64 + c) * 784 + y * 28 + xx] + lepe_b[c];
        #pragma unroll
        for (int ky = 0; ky < 3; ky++)
            #pragma unroll
            for (int kx = 0; kx < 3; kx++) {
                int xx2 = xx + kx - 1;
                if (xx2 >= 0 && xx2 < 28) a += v3[ky][c][xx2] * lepe_w[c * 9 + ky * 3 + kx];
            }
        tmp[c][xx] = a;
    }
    __syncthreads();
    for (int e = tid; e < 64 * 28; e += blockDim.x) {
        int oc = e / 28, xx = e % 28;
        float a = out_b[oc];
        const float* wr = out_w + oc * 64;
        #pragma unroll 16
        for (int c = 0; c < 64; c++) a += tmp[c][xx] * wr[c];
        outp[((size_t)b * 64 + oc) * 784 + y * 28 + xx] = a;
    }
}

// ---------------- launch ----------------
extern "C" void kernel_launch(void* const* d_in, const int* in_sizes, int n_in,
                              void* d_out, int out_size) {
    (void)in_sizes; (void)n_in; (void)out_size;
    const float* x        = (const float*)d_in[0];
    const float* norm1_g  = (const float*)d_in[1];
    const float* norm1_b  = (const float*)d_in[2];
    const float* qkv_w    = (const float*)d_in[3];
    const float* proj_w   = (const float*)d_in[4];
    const float* proj_b   = (const float*)d_in[5];
    const float* norm2_g  = (const float*)d_in[6];
    const float* norm2_b  = (const float*)d_in[7];
    const float* fc1_w    = (const float*)d_in[8];
    const float* fc1_b    = (const float*)d_in[9];
    const float* fc2_w    = (const float*)d_in[10];
    const float* fc2_b    = (const float*)d_in[11];
    const float* bf_qkv_w = (const float*)d_in[12];
    const float* bf_qkv_b = (const float*)d_in[13];
    const float* bf_lepe_w= (const float*)d_in[14];
    const float* bf_lepe_b= (const float*)d_in[15];
    const float* bf_out_w = (const float*)d_in[16];
    const float* bf_out_b = (const float*)d_in[17];
    float* out = (float*)d_out;

    float *p_h, *p_qkv, *p_att, *p_o, *p_xr, *p_h2, *p_hid;
    cudaGetSymbolAddress((void**)&p_h,   g_h);
    cudaGetSymbolAddress((void**)&p_qkv, g_qkv);
    cudaGetSymbolAddress((void**)&p_att, g_att);
    cudaGetSymbolAddress((void**)&p_o,   g_o);
    cudaGetSymbolAddress((void**)&p_xr,  g_xr);
    cudaGetSymbolAddress((void**)&p_h2,  g_h2);
    cudaGetSymbolAddress((void**)&p_hid, g_hid);

    const int MHA_SMEM = (3 * 64 * HD + 64 * 64) * 4;  // 91648 bytes
    cudaFuncSetAttribute(mha_kernel, cudaFuncAttributeMaxDynamicSharedMemorySize, MHA_SMEM);

    // 1) LN1
    ln_kernel<<<ROWS, 256>>>(x, norm1_g, norm1_b, p_h);
    // 2) qkv = h @ qkv_w  (8192 x 2352, K=784)
    gemm_kernel<0><<<dim3((3 * Cdim + 63) / 64, ROWS / 64), 256>>>(
        p_h, qkv_w, nullptr, nullptr, p_qkv, ROWS, 3 * Cdim, Cdim);
    // 3) MHA
    mha_kernel<<<dim3(NHd, Bsz), 256, MHA_SMEM>>>(p_qkv, p_att);
    // 4) o = att @ proj_w + proj_b
    gemm_kernel<0><<<dim3((Cdim + 63) / 64, ROWS / 64), 256>>>(
        p_att, proj_w, proj_b, nullptr, p_o, ROWS, Cdim, Cdim);
    // 5) BiFormer qkv
    bf_qkv_kernel<<<dim3(28, Bsz), 256>>>(p_o, bf_qkv_w, bf_qkv_b);
    // 6) region pooling
    bf_pool_kernel<<<Bsz, 256>>>();
    // 7) routing top-4
    bf_topk_kernel<<<dim3(NREG, Bsz), 64>>>();
    // 8) gathered attention
    bf_attn_kernel<<<dim3(NREG, 8, Bsz), 128>>>();
    // 9) LePE + add + out projection -> d_out second half
    bf_out_kernel<<<dim3(28, Bsz), 256>>>(bf_lepe_w, bf_lepe_b, bf_out_w, bf_out_b,
                                          out + OUT_OFF);
    // 10) xr = o + x; h2 = LN2(xr)
    ln2_kernel<<<ROWS, 256>>>(p_o, x, norm2_g, norm2_b, p_xr, p_h2);
    // 11) hid = gelu(h2 @ fc1_w + fc1_b)
    gemm_kernel<1><<<dim3(HID / 64, ROWS / 64), 256>>>(
        p_h2, fc1_w, fc1_b, nullptr, p_hid, ROWS, HID, Cdim);
    // 12) out = hid @ fc2_w + fc2_b + xr  -> d_out first half
    gemm_kernel<2><<<dim3((Cdim + 63) / 64, ROWS / 64), 256>>>(
        p_hid, fc2_w, fc2_b, p_xr, out, ROWS, Cdim, HID);
}

// round 3
// speedup vs baseline: 1.9366x; 1.9366x over previous
#include <cuda_runtime.h>
#include <cuda_bf16.h>
#include <math.h>
#include <stdint.h>

// ---------------- problem constants ----------------
#define Bsz   128
#define NTOK  64
#define Cdim  784
#define NHd   8
#define HD    98
#define HID   3136
#define ROWS  (Bsz*NTOK)  // 8192
#define NREG  49
#define TOPK  4
#define OUT_OFF (Bsz*NTOK*Cdim)

// ---------------- scratch ----------------
__device__ __nv_bfloat16 g_h_hi [ROWS*Cdim];
__device__ __nv_bfloat16 g_h_lo [ROWS*Cdim];
__device__ float         g_qkv  [ROWS*3*Cdim];
__device__ __nv_bfloat16 g_att_hi[ROWS*Cdim];
__device__ __nv_bfloat16 g_att_lo[ROWS*Cdim];
__device__ float         g_o    [ROWS*Cdim];
__device__ float         g_xr   [ROWS*Cdim];
__device__ __nv_bfloat16 g_h2_hi[ROWS*Cdim];
__device__ __nv_bfloat16 g_h2_lo[ROWS*Cdim];
__device__ __nv_bfloat16 g_hid_hi[ROWS*HID];
__device__ __nv_bfloat16 g_hid_lo[ROWS*HID];
// weight splits
__device__ __nv_bfloat16 g_wqkv_hi[Cdim*3*Cdim];
__device__ __nv_bfloat16 g_wqkv_lo[Cdim*3*Cdim];
__device__ __nv_bfloat16 g_wproj_hi[Cdim*Cdim];
__device__ __nv_bfloat16 g_wproj_lo[Cdim*Cdim];
__device__ __nv_bfloat16 g_wfc1_hi[Cdim*HID];
__device__ __nv_bfloat16 g_wfc1_lo[Cdim*HID];
__device__ __nv_bfloat16 g_wfc2_hi[HID*Cdim];
__device__ __nv_bfloat16 g_wfc2_lo[HID*Cdim];
// biformer
__device__ float g_bfqkv[Bsz*192*784];
__device__ float g_attg [Bsz*64*784];
__device__ float g_qr  [Bsz*64*NREG];
__device__ float g_kr  [Bsz*64*NREG];
__device__ int   g_idx [Bsz*NREG*TOPK];

// ---------------- helpers ----------------
__device__ __forceinline__ uint32_t smem_u32(const void* p) {
    return (uint32_t)__cvta_generic_to_shared(p);
}
#define CP_ASYNC16(dst_u32, src, sz) \
    asm volatile("cp.async.cg.shared.global [%0], [%1], 16, %2;\n" :: "r"(dst_u32), "l"(src), "r"(sz))
#define CP_COMMIT() asm volatile("cp.async.commit_group;\n")
#define CP_WAIT1()  asm volatile("cp.async.wait_group 1;\n")
#define CP_WAIT0()  asm volatile("cp.async.wait_group 0;\n")
#define LDSM4(r0,r1,r2,r3,a) \
    asm volatile("ldmatrix.sync.aligned.m8n8.x4.shared.b16 {%0,%1,%2,%3},[%4];" \
        : "=r"(r0),"=r"(r1),"=r"(r2),"=r"(r3) : "r"(a))
#define LDSM4T(r0,r1,r2,r3,a) \
    asm volatile("ldmatrix.sync.aligned.m8n8.x4.trans.shared.b16 {%0,%1,%2,%3},[%4];" \
        : "=r"(r0),"=r"(r1),"=r"(r2),"=r"(r3) : "r"(a))
#define MMA_BF16(d, a, b) \
    asm volatile("mma.sync.aligned.m16n8k16.row.col.f32.bf16.bf16.f32 " \
        "{%0,%1,%2,%3},{%4,%5,%6,%7},{%8,%9},{%0,%1,%2,%3};" \
        : "+f"(d[0]),"+f"(d[1]),"+f"(d[2]),"+f"(d[3]) \
        : "r"(a[0]),"r"(a[1]),"r"(a[2]),"r"(a[3]),"r"(b[0]),"r"(b[1]))

__device__ __forceinline__ void split_write(float v, __nv_bfloat16* hi, __nv_bfloat16* lo, size_t o) {
    __nv_bfloat16 h = __float2bfloat16(v);
    hi[o] = h;
    lo[o] = __float2bfloat16(v - __bfloat162float(h));
}

// ---------------- weight split ----------------
__global__ void split_kernel(const float* __restrict__ in, __nv_bfloat16* __restrict__ hi,
                             __nv_bfloat16* __restrict__ lo, int n) {
    int i = blockIdx.x * blockDim.x + threadIdx.x;
    if (i < n) {
        float v = in[i];
        __nv_bfloat16 h = __float2bfloat16(v);
        hi[i] = h;
        lo[i] = __float2bfloat16(v - __bfloat162float(h));
    }
}

// ---------------- LN1: x -> (h_hi, h_lo) ----------------
__global__ void ln_kernel(const float* __restrict__ x,
                          const float* __restrict__ g, const float* __restrict__ b,
                          __nv_bfloat16* __restrict__ ohi, __nv_bfloat16* __restrict__ olo) {
    int row = blockIdx.x;
    const float* xr = x + (size_t)row * Cdim;
    __shared__ float buf[Cdim];
    __shared__ float rs[2];
    __shared__ float red[64];
    float s = 0.f, ss = 0.f;
    for (int i = threadIdx.x; i < Cdim; i += blockDim.x) {
        float v = xr[i]; buf[i] = v; s += v; ss += v * v;
    }
    for (int o = 16; o > 0; o >>= 1) { s += __shfl_down_sync(~0u, s, o); ss += __shfl_down_sync(~0u, ss, o); }
    int wid = threadIdx.x >> 5, lid = threadIdx.x & 31;
    if (lid == 0) { red[wid] = s; red[wid + 32] = ss; }
    __syncthreads();
    if (threadIdx.x == 0) {
        float t = 0.f, tt = 0.f;
        int nw = blockDim.x >> 5;
        for (int i = 0; i < nw; i++) { t += red[i]; tt += red[i + 32]; }
        float mean = t / Cdim, var = tt / Cdim - mean * mean;
        rs[0] = mean; rs[1] = rsqrtf(var + 1e-5f);
    }
    __syncthreads();
    float mean = rs[0], inv = rs[1];
    for (int i = threadIdx.x; i < Cdim; i += blockDim.x)
        split_write((buf[i] - mean) * inv * g[i] + b[i], ohi, olo, (size_t)row * Cdim + i);
}

// ---------------- LN2: xr = o + x (fp32 out), h2 split ----------------
__global__ void ln2_kernel(const float* __restrict__ ov, const float* __restrict__ x,
                           const float* __restrict__ g, const float* __restrict__ b,
                           float* __restrict__ xr_out,
                           __nv_bfloat16* __restrict__ ohi, __nv_bfloat16* __restrict__ olo) {
    int row = blockIdx.x;
    const float* a = ov + (size_t)row * Cdim;
    const float* c = x  + (size_t)row * Cdim;
    __shared__ float buf[Cdim];
    __shared__ float rs[2];
    __shared__ float red[64];
    float s = 0.f, ss = 0.f;
    for (int i = threadIdx.x; i < Cdim; i += blockDim.x) {
        float v = a[i] + c[i];
        buf[i] = v;
        xr_out[(size_t)row * Cdim + i] = v;
        s += v; ss += v * v;
    }
    for (int o = 16; o > 0; o >>= 1) { s += __shfl_down_sync(~0u, s, o); ss += __shfl_down_sync(~0u, ss, o); }
    int wid = threadIdx.x >> 5, lid = threadIdx.x & 31;
    if (lid == 0) { red[wid] = s; red[wid + 32] = ss; }
    __syncthreads();
    if (threadIdx.x == 0) {
        float t = 0.f, tt = 0.f;
        int nw = blockDim.x >> 5;
        for (int i = 0; i < nw; i++) { t += red[i]; tt += red[i + 32]; }
        float mean = t / Cdim, var = tt / Cdim - mean * mean;
        rs[0] = mean; rs[1] = rsqrtf(var + 1e-5f);
    }
    __syncthreads();
    float mean = rs[0], inv = rs[1];
    for (int i = threadIdx.x; i < Cdim; i += blockDim.x)
        split_write((buf[i] - mean) * inv * g[i] + b[i], ohi, olo, (size_t)row * Cdim + i);
}

// ---------------- bf16x3 tensor-core GEMM ----------------
// C[M,N] = A[M,K] @ B[K,N], A/B given as (hi,lo) bf16 splits, fp32 accumulate.
// EP: 0 plain fp32 out; 1 +bias fp32 out; 2 +bias, GELU, split-bf16 out; 3 +bias +res fp32 out
#define BM 128
#define BN 128
#define BK 16
#define ASTR 24
#define BSTR 136

template<int EP>
__global__ __launch_bounds__(256, 1)
void mma_gemm(const __nv_bfloat16* __restrict__ Ah, const __nv_bfloat16* __restrict__ Al,
              const __nv_bfloat16* __restrict__ Bh, const __nv_bfloat16* __restrict__ Bl,
              const float* __restrict__ bias, const float* __restrict__ res,
              float* __restrict__ Cf, __nv_bfloat16* __restrict__ Chi, __nv_bfloat16* __restrict__ Clo,
              int M, int N, int K) {
    __shared__ __nv_bfloat16 As[2][2][BM][ASTR];
    __shared__ __nv_bfloat16 Bs[2][2][BK][BSTR];
    int tid = threadIdx.x;
    int warp = tid >> 5, lane = tid & 31;
    int wm = warp & 1, wn = warp >> 1;          // 2 x 4 warp grid
    int rowBase = blockIdx.y * BM, colBase = blockIdx.x * BN;

    int a_row = tid >> 1;                        // 0..127
    int a_col = (tid & 1) * 8;                   // 0/8
    int b_row = tid >> 4;                        // 0..15
    int b_col = (tid & 15) * 8;                  // 0..120
    int gcol  = colBase + b_col;
    int bsz   = (gcol < N) ? 16 : 0;

    const int KT = K / BK;
    float acc[4][4][4];
    #pragma unroll
    for (int i = 0; i < 4; i++)
        #pragma unroll
        for (int j = 0; j < 4; j++)
            #pragma unroll
            for (int k = 0; k < 4; k++) acc[i][j][k] = 0.f;

    // precomputed smem write addresses
    uint32_t sAh[2], sAl[2], sBh[2], sBl[2];
    #pragma unroll
    for (int bf = 0; bf < 2; bf++) {
        sAh[bf] = smem_u32(&As[bf][0][a_row][a_col]);
        sAl[bf] = smem_u32(&As[bf][1][a_row][a_col]);
        sBh[bf] = smem_u32(&Bs[bf][0][b_row][b_col]);
        sBl[bf] = smem_u32(&Bs[bf][1][b_row][b_col]);
    }
    // ldmatrix read addresses (per buffer, hi/lo)
    int lrow = lane & 15, lhalf = (lane >> 4) * 8;

    // prologue: stage 0
    {
        size_t a_off = (size_t)(rowBase + a_row) * K + a_col;
        CP_ASYNC16(sAh[0], Ah + a_off, 16);
        CP_ASYNC16(sAl[0], Al + a_off, 16);
        size_t b_off = (size_t)b_row * N + gcol;
        const __nv_bfloat16* ph = (bsz ? Bh + b_off : Bh);
        const __nv_bfloat16* pl = (bsz ? Bl + b_off : Bl);
        CP_ASYNC16(sBh[0], ph, bsz);
        CP_ASYNC16(sBl[0], pl, bsz);
        CP_COMMIT();
    }

    for (int kt = 0; kt < KT; kt++) {
        if (kt + 1 < KT) {
            int bf = (kt + 1) & 1;
            size_t a_off = (size_t)(rowBase + a_row) * K + (kt + 1) * BK + a_col;
            CP_ASYNC16(sAh[bf], Ah + a_off, 16);
            CP_ASYNC16(sAl[bf], Al + a_off, 16);
            size_t b_off = (size_t)((kt + 1) * BK + b_row) * N + gcol;
            const __nv_bfloat16* ph = (bsz ? Bh + b_off : Bh);
            const __nv_bfloat16* pl = (bsz ? Bl + b_off : Bl);
            CP_ASYNC16(sBh[bf], ph, bsz);
            CP_ASYNC16(sBl[bf], pl, bsz);
            CP_COMMIT();
            CP_WAIT1();
        } else {
            CP_WAIT0();
        }
        __syncthreads();
        int bf = kt & 1;

        uint32_t ah[4][4], al[4][4], bh[4][2], bl[4][2];
        #pragma unroll
        for (int mi = 0; mi < 4; mi++) {
            uint32_t a0 = smem_u32(&As[bf][0][wm * 64 + mi * 16 + lrow][lhalf]);
            LDSM4(ah[mi][0], ah[mi][1], ah[mi][2], ah[mi][3], a0);
            uint32_t a1 = smem_u32(&As[bf][1][wm * 64 + mi * 16 + lrow][lhalf]);
            LDSM4(al[mi][0], al[mi][1], al[mi][2], al[mi][3], a1);
        }
        #pragma unroll
        for (int pr = 0; pr < 2; pr++) {
            uint32_t r0, r1, r2, r3;
            uint32_t b0 = smem_u32(&Bs[bf][0][lrow][wn * 32 + pr * 16 + lhalf]);
            LDSM4T(r0, r1, r2, r3, b0);
            bh[pr * 2][0] = r0; bh[pr * 2][1] = r1; bh[pr * 2 + 1][0] = r2; bh[pr * 2 + 1][1] = r3;
            uint32_t b1 = smem_u32(&Bs[bf][1][lrow][wn * 32 + pr * 16 + lhalf]);
            LDSM4T(r0, r1, r2, r3, b1);
            bl[pr * 2][0] = r0; bl[pr * 2][1] = r1; bl[pr * 2 + 1][0] = r2; bl[pr * 2 + 1][1] = r3;
        }
        #pragma unroll
        for (int mi = 0; mi < 4; mi++)
            #pragma unroll
            for (int ni = 0; ni < 4; ni++) {
                MMA_BF16(acc[mi][ni], ah[mi], bh[ni]);
                MMA_BF16(acc[mi][ni], ah[mi], bl[ni]);
                MMA_BF16(acc[mi][ni], al[mi], bh[ni]);
            }
        __syncthreads();
    }

    // epilogue
    #pragma unroll
    for (int mi = 0; mi < 4; mi++) {
        int r0 = rowBase + wm * 64 + mi * 16 + (lane >> 2);
        #pragma unroll
        for (int ni = 0; ni < 4; ni++) {
            int c0 = colBase + wn * 32 + ni * 8 + (lane & 3) * 2;
            #pragma unroll
            for (int q = 0; q < 4; q++) {
                int r = r0 + (q >> 1) * 8;
                int c = c0 + (q & 1);
                if (c < N) {
                    float v = acc[mi][ni][q];
                    if (EP >= 1) v += bias[c];
                    size_t o = (size_t)r * N + c;
                    if (EP == 2) {
                        v = 0.5f * v * (1.0f + erff(v * 0.70710678118654752440f));
                        split_write(v, Chi, Clo, o);
                    } else {
                        if (EP == 3) v += res[o];
                        Cf[o] = v;
                    }
                }
            }
        }
    }
}

// ---------------- MHA: block per (head, batch); writes att split ----------------
__global__ void mha_kernel(const float* __restrict__ qkv,
                           __nv_bfloat16* __restrict__ ahi, __nv_bfloat16* __restrict__ alo) {
    extern __shared__ float sm[];
    float* Q  = sm;
    float* Kx = Q + 64 * HD;
    float* V  = Kx + 64 * HD;
    float* SC = V + 64 * HD;
    int h = blockIdx.x, b = blockIdx.y;
    int tid = threadIdx.x;
    const float* base = qkv + (size_t)(b * NTOK) * (3 * Cdim);
    for (int e = tid; e < 64 * HD; e += blockDim.x) {
        int t = e / HD, d = e % HD;
        Q[e]  = base[(size_t)t * (3 * Cdim) + h * HD + d];
        Kx[e] = base[(size_t)t * (3 * Cdim) + Cdim + h * HD + d];
        V[e]  = base[(size_t)t * (3 * Cdim) + 2 * Cdim + h * HD + d];
    }
    __syncthreads();
    const float scale = rsqrtf((float)HD);
    for (int e = tid; e < 64 * 64; e += blockDim.x) {
        int i = e >> 6, j = e & 63;
        float a = 0.f;
        const float* qi = Q + i * HD;
        const float* kj = Kx + j * HD;
        #pragma unroll 7
        for (int d = 0; d < HD; d++) a += qi[d] * kj[d];
        SC[e] = a * scale;
    }
    __syncthreads();
    if (tid < 64) {
        float* row = SC + tid * 64;
        float mx = -1e30f;
        for (int j = 0; j < 64; j++) mx = fmaxf(mx, row[j]);
        float s = 0.f;
        for (int j = 0; j < 64; j++) { float e = expf(row[j] - mx); row[j] = e; s += e; }
        float inv = 1.f / s;
        for (int j = 0; j < 64; j++) row[j] *= inv;
    }
    __syncthreads();
    for (int e = tid; e < 64 * HD; e += blockDim.x) {
        int i = e / HD, d = e % HD;
        float a = 0.f;
        const float* row = SC + i * 64;
        for (int j = 0; j < 64; j++) a += row[j] * V[j * HD + d];
        split_write(a, ahi, alo, ((size_t)(b * NTOK + i)) * Cdim + h * HD + d);
    }
}

// ---------------- BiFormer (unchanged fp32, small) ----------------
__global__ void bf_qkv_kernel(const float* __restrict__ o,
                              const float* __restrict__ w, const float* __restrict__ bias) {
    int y = blockIdx.x, b = blockIdx.y;
    __shared__ float xin[64][28];
    for (int e = threadIdx.x; e < 64 * 28; e += blockDim.x) {
        int c = e / 28, xx = e % 28;
        xin[c][xx] = o[((size_t)b * 64 + c) * 784 + y * 28 + xx];
    }
    __syncthreads();
    for (int e = threadIdx.x; e < 192 * 28; e += blockDim.x) {
        int oc = e / 28, xx = e % 28;
        float a = bias[oc];
        const float* wr = w + oc * 64;
        #pragma unroll 16
        for (int c = 0; c < 64; c++) a += xin[c][xx] * wr[c];
        g_bfqkv[((size_t)b * 192 + oc) * 784 + y * 28 + xx] = a;
    }
}

__global__ void bf_pool_kernel() {
    int b = blockIdx.x;
    for (int e = threadIdx.x; e < 64 * NREG; e += blockDim.x) {
        int c = e / NREG, r = e % NREG;
        int rh = r / 7, rw = r % 7;
        float sq = 0.f, sk = 0.f;
        const float* qc = g_bfqkv + ((size_t)b * 192 + c) * 784;
        const float* kc = g_bfqkv + ((size_t)b * 192 + 64 + c) * 784;
        for (int pr = 0; pr < 4; pr++)
            for (int pc = 0; pc < 4; pc++) {
                int s = (rh * 4 + pr) * 28 + rw * 4 + pc;
                sq += qc[s]; sk += kc[s];
            }
        g_qr[(b * 64 + c) * NREG + r] = sq * 0.0625f;
        g_kr[(b * 64 + c) * NREG + r] = sk * 0.0625f;
    }
}

__global__ void bf_topk_kernel() {
    int r = blockIdx.x, b = blockIdx.y;
    __shared__ float qv[64];
    __shared__ float sc[NREG];
    int tid = threadIdx.x;
    if (tid < 64) qv[tid] = g_qr[(b * 64 + tid) * NREG + r];
    __syncthreads();
    if (tid < NREG) {
        float a = 0.f;
        for (int c = 0; c < 64; c++) a += qv[c] * g_kr[(b * 64 + c) * NREG + tid];
        sc[tid] = a;
    }
    __syncthreads();
    if (tid == 0) {
        for (int j = 0; j < TOPK; j++) {
            float mx = -1e30f; int mi = 0;
            for (int s = 0; s < NREG; s++) if (sc[s] > mx) { mx = sc[s]; mi = s; }
            sc[mi] = -1e30f;
            g_idx[(b * NREG + r) * TOPK + j] = mi;
        }
    }
}

__global__ void bf_attn_kernel() {
    int r = blockIdx.x, h = blockIdx.y, b = blockIdx.z;
    __shared__ float q[16][8], kg[64][8], vg[64][8], sc[16][64];
    __shared__ int idx4[4];
    int tid = threadIdx.x;
    if (tid < 4) idx4[tid] = g_idx[(b * NREG + r) * TOPK + tid];
    int rh = r / 7, rw = r % 7;
    {
        int p = tid / 8, d = tid % 8;
        int s = (rh * 4 + p / 4) * 28 + rw * 4 + (p % 4);
        q[p][d] = g_bfqkv[((size_t)b * 192 + h * 8 + d) * 784 + s] * 0.125f;
    }
    __syncthreads();
    for (int e = tid; e < 512; e += 128) {
        int t = e / 8, d = e % 8;
        int reg = idx4[t / 16];
        int p2 = t % 16;
        int s = ((reg / 7) * 4 + p2 / 4) * 28 + (reg % 7) * 4 + (p2 % 4);
        kg[t][d] = g_bfqkv[((size_t)b * 192 + 64 + h * 8 + d) * 784 + s];
        vg[t][d] = g_bfqkv[((size_t)b * 192 + 128 + h * 8 + d) * 784 + s];
    }
    __syncthreads();
    for (int e = tid; e < 1024; e += 128) {
        int p = e >> 6, t = e & 63;
        float a = 0.f;
        #pragma unroll
        for (int d = 0; d < 8; d++) a += q[p][d] * kg[t][d];
        sc[p][t] = a;
    }
    __syncthreads();
    if (tid < 16) {
        float mx = -1e30f;
        for (int t = 0; t < 64; t++) mx = fmaxf(mx, sc[tid][t]);
        float s = 0.f;
        for (int t = 0; t < 64; t++) { float e = expf(sc[tid][t] - mx); sc[tid][t] = e; s += e; }
        float inv = 1.f / s;
        for (int t = 0; t < 64; t++) sc[tid][t] *= inv;
    }
    __syncthreads();
    {
        int p = tid / 8, d = tid % 8;
        float a = 0.f;
        for (int t = 0; t < 64; t++) a += sc[p][t] * vg[t][d];
        int s = (rh * 4 + p / 4) * 28 + rw * 4 + (p % 4);
        g_attg[((size_t)b * 64 + h * 8 + d) * 784 + s] = a;
    }
}

__global__ void bf_out_kernel(const float* __restrict__ lepe_w, const float* __restrict__ lepe_b,
                              const float* __restrict__ out_w, const float* __restrict__ out_b,
                              float* __restrict__ outp) {
    int y = blockIdx.x, b = blockIdx.y;
    __shared__ float v3[3][64][28];
    __shared__ float tmp[64][28];
    int tid = threadIdx.x;
    for (int ry = 0; ry < 3; ry++) {
        int yy = y + ry - 1;
        for (int e = tid; e < 64 * 28; e += blockDim.x) {
            int c = e / 28, xx = e % 28;
            v3[ry][c][xx] = (yy >= 0 && yy < 28)
                ? g_bfqkv[((size_t)b * 192 + 128 + c) * 784 + yy * 28 + xx] : 0.f;
        }
    }
    __syncthreads();
    for (int e = tid; e < 64 * 28; e += blockDim.x) {
        int c = e / 28, xx = e % 28;
        float a = g_attg[((size_t)b * 64 + c) * 784 + y * 28 + xx] + lepe_b[c];
        #pragma unroll
        for (int ky = 0; ky < 3; ky++)
            #pragma unroll
            for (int kx = 0; kx < 3; kx++) {
                int xx2 = xx + kx - 1;
                if (xx2 >= 0 && xx2 < 28) a += v3[ky][c][xx2] * lepe_w[c * 9 + ky * 3 + kx];
            }
        tmp[c][xx] = a;
    }
    __syncthreads();
    for (int e = tid; e < 64 * 28; e += blockDim.x) {
        int oc = e / 28, xx = e % 28;
        float a = out_b[oc];
        const float* wr = out_w + oc * 64;
        #pragma unroll 16
        for (int c = 0; c < 64; c++) a += tmp[c][xx] * wr[c];
        outp[((size_t)b * 64 + oc) * 784 + y * 28 + xx] = a;
    }
}

// ---------------- launch ----------------
extern "C" void kernel_launch(void* const* d_in, const int* in_sizes, int n_in,
                              void* d_out, int out_size) {
    (void)in_sizes; (void)n_in; (void)out_size;
    const float* x        = (const float*)d_in[0];
    const float* norm1_g  = (const float*)d_in[1];
    const float* norm1_b  = (const float*)d_in[2];
    const float* qkv_w    = (const float*)d_in[3];
    const float* proj_w   = (const float*)d_in[4];
    const float* proj_b   = (const float*)d_in[5];
    const float* norm2_g  = (const float*)d_in[6];
    const float* norm2_b  = (const float*)d_in[7];
    const float* fc1_w    = (const float*)d_in[8];
    const float* fc1_b    = (const float*)d_in[9];
    const float* fc2_w    = (const float*)d_in[10];
    const float* fc2_b    = (const float*)d_in[11];
    const float* bf_qkv_w = (const float*)d_in[12];
    const float* bf_qkv_b = (const float*)d_in[13];
    const float* bf_lepe_w= (const float*)d_in[14];
    const float* bf_lepe_b= (const float*)d_in[15];
    const float* bf_out_w = (const float*)d_in[16];
    const float* bf_out_b = (const float*)d_in[17];
    float* out = (float*)d_out;

    __nv_bfloat16 *p_h_hi, *p_h_lo, *p_att_hi, *p_att_lo, *p_h2_hi, *p_h2_lo, *p_hid_hi, *p_hid_lo;
    __nv_bfloat16 *p_wqkv_hi, *p_wqkv_lo, *p_wproj_hi, *p_wproj_lo, *p_wfc1_hi, *p_wfc1_lo, *p_wfc2_hi, *p_wfc2_lo;
    float *p_qkv, *p_o, *p_xr;
    cudaGetSymbolAddress((void**)&p_h_hi, g_h_hi);     cudaGetSymbolAddress((void**)&p_h_lo, g_h_lo);
    cudaGetSymbolAddress((void**)&p_att_hi, g_att_hi); cudaGetSymbolAddress((void**)&p_att_lo, g_att_lo);
    cudaGetSymbolAddress((void**)&p_h2_hi, g_h2_hi);   cudaGetSymbolAddress((void**)&p_h2_lo, g_h2_lo);
    cudaGetSymbolAddress((void**)&p_hid_hi, g_hid_hi); cudaGetSymbolAddress((void**)&p_hid_lo, g_hid_lo);
    cudaGetSymbolAddress((void**)&p_wqkv_hi, g_wqkv_hi);   cudaGetSymbolAddress((void**)&p_wqkv_lo, g_wqkv_lo);
    cudaGetSymbolAddress((void**)&p_wproj_hi, g_wproj_hi); cudaGetSymbolAddress((void**)&p_wproj_lo, g_wproj_lo);
    cudaGetSymbolAddress((void**)&p_wfc1_hi, g_wfc1_hi);   cudaGetSymbolAddress((void**)&p_wfc1_lo, g_wfc1_lo);
    cudaGetSymbolAddress((void**)&p_wfc2_hi, g_wfc2_hi);   cudaGetSymbolAddress((void**)&p_wfc2_lo, g_wfc2_lo);
    cudaGetSymbolAddress((void**)&p_qkv, g_qkv);
    cudaGetSymbolAddress((void**)&p_o, g_o);
    cudaGetSymbolAddress((void**)&p_xr, g_xr);

    const int MHA_SMEM = (3 * 64 * HD + 64 * 64) * 4;
    cudaFuncSetAttribute(mha_kernel, cudaFuncAttributeMaxDynamicSharedMemorySize, MHA_SMEM);

    // weight splits
    split_kernel<<<(Cdim * 3 * Cdim + 255) / 256, 256>>>(qkv_w,  p_wqkv_hi,  p_wqkv_lo,  Cdim * 3 * Cdim);
    split_kernel<<<(Cdim * Cdim + 255) / 256, 256>>>(proj_w, p_wproj_hi, p_wproj_lo, Cdim * Cdim);
    split_kernel<<<(Cdim * HID + 255) / 256, 256>>>(fc1_w,  p_wfc1_hi,  p_wfc1_lo,  Cdim * HID);
    split_kernel<<<(HID * Cdim + 255) / 256, 256>>>(fc2_w,  p_wfc2_hi,  p_wfc2_lo,  HID * Cdim);

    // 1) LN1 -> h split
    ln_kernel<<<ROWS, 256>>>(x, norm1_g, norm1_b, p_h_hi, p_h_lo);
    // 2) qkv = h @ qkv_w (fp32)
    mma_gemm<0><<<dim3((3 * Cdim + BN - 1) / BN, ROWS / BM), 256>>>(
        p_h_hi, p_h_lo, p_wqkv_hi, p_wqkv_lo, nullptr, nullptr,
        p_qkv, nullptr, nullptr, ROWS, 3 * Cdim, Cdim);
    // 3) MHA -> att split
    mha_kernel<<<dim3(NHd, Bsz), 256, MHA_SMEM>>>(p_qkv, p_att_hi, p_att_lo);
    // 4) o = att @ proj_w + proj_b (fp32)
    mma_gemm<1><<<dim3((Cdim + BN - 1) / BN, ROWS / BM), 256>>>(
        p_att_hi, p_att_lo, p_wproj_hi, p_wproj_lo, proj_b, nullptr,
        p_o, nullptr, nullptr, ROWS, Cdim, Cdim);
    // 5-9) BiFormer branch
    bf_qkv_kernel<<<dim3(28, Bsz), 256>>>(p_o, bf_qkv_w, bf_qkv_b);
    bf_pool_kernel<<<Bsz, 256>>>();
    bf_topk_kernel<<<dim3(NREG, Bsz), 64>>>();
    bf_attn_kernel<<<dim3(NREG, 8, Bsz), 128>>>();
    bf_out_kernel<<<dim3(28, Bsz), 256>>>(bf_lepe_w, bf_lepe_b, bf_out_w, bf_out_b, out + OUT_OFF);
    // 10) LN2
    ln2_kernel<<<ROWS, 256>>>(p_o, x, norm2_g, norm2_b, p_xr, p_h2_hi, p_h2_lo);
    // 11) hid = gelu(h2 @ fc1_w + b) -> split
    mma_gemm<2><<<dim3((HID + BN - 1) / BN, ROWS / BM), 256>>>(
        p_h2_hi, p_h2_lo, p_wfc1_hi, p_wfc1_lo, fc1_b, nullptr,
        nullptr, p_hid_hi, p_hid_lo, ROWS, HID, Cdim);
    // 12) out = hid @ fc2_w + b + xr
    mma_gemm<3><<<dim3((Cdim + BN - 1) / BN, ROWS / BM), 256>>>(
        p_hid_hi, p_hid_lo, p_wfc2_hi, p_wfc2_lo, fc2_b, p_xr,
        out, nullptr, nullptr, ROWS, Cdim, HID);
}